// round 15
// baseline (speedup 1.0000x reference)
#include <cuda_runtime.h>
#include <cstdint>

// VLPLLoss: sampled Plackett-Luce counterfactual expected reward.
//   d_in[0] y_pred : float32 [B, D, 1]   B=4096, D=120
//   d_in[1] y_true : float32 [B, D, 1]
//   d_in[2] pO_slot: float32 [K]         K=10
//   d_in[3] gumbel : float32 [S, B, D]   S=128
// out: scalar mean over (s,b) of sum_k pO[k] * y_true[b, topk_idx(s,b,k)]
//
// R15: cp.async prefetch (GMEM->SMEM, no register staging) -> regs ~46,
// __launch_bounds__(128,10) -> 10 blocks/SM (62.5% occ). y_pred add moved
// into the key build (broadcast LDS + FADD on the idle fma pipe). Everything
// else from the proven R11/R14 line: pruned Batcher top10of16 (60 CE),
// half-cleaner + clean10v merge (25 ops), STR=20 conflict-free LDS.128,
// reversed y_true gather, fixed-point single-kernel reduction.
// Keys: bits(v) low 7 mantissa bits = (127 - doc), v = y_pred+gumbel+32 > 0
// -> uint order == float order, keys distinct, smaller doc wins ties (== top_k).

#define B_DIM 4096
#define D_DIM 120
#define S_DIM 128
#define K_SLOTS 10
#define ROWS_TOTAL (B_DIM * S_DIM)
#define BD_STRIDE (B_DIM * D_DIM)
#define STR 20   // smem row stride in floats

__device__ unsigned long long g_total = 0ull;
__device__ unsigned int g_count = 0u;

__device__ __forceinline__ void cp_async16(uint32_t saddr, const float* gptr) {
    asm volatile("cp.async.ca.shared.global [%0], [%1], 16;\n"
                 :: "r"(saddr), "l"(gptr) : "memory");
}
__device__ __forceinline__ void cp_commit() {
    asm volatile("cp.async.commit_group;\n" ::: "memory");
}
__device__ __forceinline__ void cp_wait0() {
    asm volatile("cp.async.wait_group 0;\n" ::: "memory");
}

// compare-exchange: ensure x >= y (IMNMX pair)
__device__ __forceinline__ void ce(unsigned& x, unsigned& y) {
    unsigned a = x, b = y;
    x = max(a, b);
    y = min(a, b);
}

// Batcher sort16 pruned to outputs 0..9 (sorted-desc top-10), 60 CE.
__device__ __forceinline__ void top10of16(unsigned* c) {
    ce(c[0],c[1]); ce(c[2],c[3]); ce(c[4],c[5]); ce(c[6],c[7]);
    ce(c[8],c[9]); ce(c[10],c[11]); ce(c[12],c[13]); ce(c[14],c[15]);
    ce(c[0],c[2]); ce(c[1],c[3]); ce(c[4],c[6]); ce(c[5],c[7]);
    ce(c[8],c[10]); ce(c[9],c[11]); ce(c[12],c[14]); ce(c[13],c[15]);
    ce(c[1],c[2]); ce(c[5],c[6]); ce(c[9],c[10]); ce(c[13],c[14]);
    ce(c[0],c[4]); ce(c[1],c[5]); ce(c[2],c[6]); ce(c[3],c[7]);
    ce(c[8],c[12]); ce(c[9],c[13]); ce(c[10],c[14]); ce(c[11],c[15]);
    ce(c[2],c[4]); ce(c[3],c[5]); ce(c[10],c[12]); ce(c[11],c[13]);
    ce(c[1],c[2]); ce(c[3],c[4]); ce(c[5],c[6]);
    ce(c[9],c[10]); ce(c[11],c[12]); ce(c[13],c[14]);
    ce(c[0],c[8]); ce(c[1],c[9]); ce(c[2],c[10]); ce(c[3],c[11]);
    ce(c[4],c[12]); ce(c[5],c[13]); ce(c[6],c[14]); ce(c[7],c[15]);
    ce(c[4],c[8]); ce(c[5],c[9]); ce(c[6],c[10]); ce(c[7],c[11]);
    ce(c[2],c[4]); ce(c[3],c[5]); ce(c[6],c[8]); ce(c[7],c[9]); ce(c[10],c[12]);
    ce(c[1],c[2]); ce(c[3],c[4]); ce(c[5],c[6]); ce(c[7],c[8]); ce(c[9],c[10]);
}

// Batcher sort8 descending (19 CE)
__device__ __forceinline__ void sort8(unsigned* c) {
    ce(c[0],c[1]); ce(c[2],c[3]); ce(c[4],c[5]); ce(c[6],c[7]);
    ce(c[0],c[2]); ce(c[1],c[3]); ce(c[4],c[6]); ce(c[5],c[7]);
    ce(c[1],c[2]); ce(c[5],c[6]);
    ce(c[0],c[4]); ce(c[1],c[5]); ce(c[2],c[6]); ce(c[3],c[7]);
    ce(c[2],c[4]); ce(c[3],c[5]);
    ce(c[1],c[2]); ce(c[3],c[4]); ce(c[5],c[6]);
}

// Bitonic cleanup for a length-10 valley (desc-then-asc) sequence (15 CE).
// Derivation: front-pad with +inf to 16 -> clean16's effective comparators.
__device__ __forceinline__ void clean10v(unsigned* m) {
    ce(m[0],m[8]); ce(m[1],m[9]);
    ce(m[0],m[1]);
    ce(m[2],m[6]); ce(m[3],m[7]); ce(m[4],m[8]); ce(m[5],m[9]);
    ce(m[2],m[4]); ce(m[3],m[5]); ce(m[6],m[8]); ce(m[7],m[9]);
    ce(m[2],m[3]); ce(m[4],m[5]); ce(m[6],m[7]); ce(m[8],m[9]);
}

__global__ __launch_bounds__(S_DIM, 10) void vlpl_kernel(
    const float* __restrict__ y_pred,
    const float* __restrict__ y_true,
    const float* __restrict__ pO,
    const float* __restrict__ gumbel,
    float* __restrict__ out)
{
    __shared__ __align__(16) float g_sh[2][S_DIM * STR];  // raw gumbel chunks
    __shared__ __align__(16) float yp_sh[D_DIM];
    __shared__ float yt_sh[S_DIM];      // reversed: yt_sh[127-d] = y_true[d]
    __shared__ float po_sh[K_SLOTS];
    __shared__ float wsum[4];

    const int b = blockIdx.x;
    const int t = threadIdx.x;

    if (t < D_DIM) {
        yp_sh[t] = y_pred[b * D_DIM + t] + 32.0f;
        yt_sh[127 - t] = y_true[b * D_DIM + t];
    }
    if (t < K_SLOTS) po_sh[t] = pO[t];

    const size_t gb = (size_t)b * D_DIM;
    const int jf  = (t & 3) * 4;   // float offset within a 16-doc chunk row
    const int r0  = t >> 2;        // base row for the 16-wide loader
    const int jf8 = (t & 1) * 4;   // remainder-loader geometry
    const int r8  = t >> 1;
    const float* __restrict__ gbase = gumbel + gb + (size_t)r0 * BD_STRIDE + jf;
    const float* __restrict__ gb8 =
        gumbel + gb + (size_t)r8 * BD_STRIDE + 112 + jf8;

    // smem byte addresses for this thread's cp.async destinations
    const uint32_t s_main =
        (uint32_t)__cvta_generic_to_shared(&g_sh[0][r0 * STR + jf]);
    const uint32_t s_rem =
        (uint32_t)__cvta_generic_to_shared(&g_sh[0][r8 * STR + jf8]);
    const uint32_t BUF = (uint32_t)(S_DIM * STR * sizeof(float));
    const uint32_t ROWB = (uint32_t)(STR * sizeof(float));

    // ---- prologue: cp.async chunk 0 -> buffer 0 ----
#pragma unroll
    for (int q = 0; q < 4; ++q)
        cp_async16(s_main + q * 32 * ROWB, gbase + (size_t)q * 32 * BD_STRIDE);
    cp_commit();
    cp_wait0();
    __syncthreads();

    unsigned L[10];
#pragma unroll
    for (int i = 0; i < 10; ++i) L[i] = 0u;

#pragma unroll 1
    for (int c = 0; c < 7; ++c) {
        // ---- (1) cp.async next chunk into the other buffer ----
        const uint32_t dst = ((c + 1) & 1) ? BUF : 0u;
        if (c < 6) {
            const float* p = gbase + (c + 1) * 16;
#pragma unroll
            for (int q = 0; q < 4; ++q)
                cp_async16(s_main + dst + q * 32 * ROWB,
                           p + (size_t)q * 32 * BD_STRIDE);
        } else {
            cp_async16(s_rem + BUF, gb8);
            cp_async16(s_rem + BUF + 64 * ROWB, gb8 + (size_t)64 * BD_STRIDE);
        }
        cp_commit();

        // ---- (2) compute chunk c from buffer c&1 (hides cp.async latency) ----
        unsigned C[16];
        {
            const float* row = &g_sh[c & 1][t * STR];
            const float* ypc = &yp_sh[c * 16];
#pragma unroll
            for (int q = 0; q < 4; ++q) {
                const float4 v = *reinterpret_cast<const float4*>(row + 4 * q);
                const float4 y = *reinterpret_cast<const float4*>(ypc + 4 * q);
                const unsigned lb = (unsigned)(127 - c * 16 - 4 * q);
                C[4*q+0] = (__float_as_uint(y.x + v.x) & 0xFFFFFF80u) | lb;
                C[4*q+1] = (__float_as_uint(y.y + v.y) & 0xFFFFFF80u) | (lb - 1u);
                C[4*q+2] = (__float_as_uint(y.z + v.z) & 0xFFFFFF80u) | (lb - 2u);
                C[4*q+3] = (__float_as_uint(y.w + v.w) & 0xFFFFFF80u) | (lb - 3u);
            }
        }
        top10of16(C);
        // merge two sorted-desc-10: half-cleaner pairs, then valley cleanup
#pragma unroll
        for (int i = 0; i < 10; ++i) L[i] = max(L[i], C[9 - i]);
        clean10v(L);

        // ---- (3) drain the prefetch, publish buffer ----
        cp_wait0();
        __syncthreads();
    }

    // ---- remainder compute: docs 112..119 from buffer 1 ----
    {
        unsigned C[8];
        const float* row = &g_sh[1][t * STR];
        const float* ypc = &yp_sh[112];
#pragma unroll
        for (int q = 0; q < 2; ++q) {
            const float4 v = *reinterpret_cast<const float4*>(row + 4 * q);
            const float4 y = *reinterpret_cast<const float4*>(ypc + 4 * q);
            const unsigned lb = (unsigned)(15 - 4 * q);
            C[4*q+0] = (__float_as_uint(y.x + v.x) & 0xFFFFFF80u) | lb;
            C[4*q+1] = (__float_as_uint(y.y + v.y) & 0xFFFFFF80u) | (lb - 1u);
            C[4*q+2] = (__float_as_uint(y.z + v.z) & 0xFFFFFF80u) | (lb - 2u);
            C[4*q+3] = (__float_as_uint(y.w + v.w) & 0xFFFFFF80u) | (lb - 3u);
        }
        sort8(C);
        // pad C[8]=C[9]=0 -> L[0],L[1] untouched by the half-cleaner stage
#pragma unroll
        for (int i = 2; i < 10; ++i) L[i] = max(L[i], C[9 - i]);
        clean10v(L);
    }

    // ---- decode top-10 (yt stored reversed -> direct index), weighted sum ----
    float reward = 0.0f;
#pragma unroll
    for (int k = 0; k < K_SLOTS; ++k)
        reward += po_sh[k] * yt_sh[(int)(L[k] & 127u)];

    // ---- deterministic reduction: warp shuffle + fixed-point global atomic ----
#pragma unroll
    for (int off = 16; off > 0; off >>= 1)
        reward += __shfl_down_sync(0xFFFFFFFFu, reward, off);
    if ((t & 31) == 0) wsum[t >> 5] = reward;
    __syncthreads();

    if (t == 0) {
        const float part = (wsum[0] + wsum[1]) + (wsum[2] + wsum[3]);
        // rewards nonnegative; block partial <= 1280 -> fits with 2^32 scale
        const unsigned long long fx =
            (unsigned long long)((double)part * 4294967296.0);
        atomicAdd(&g_total, fx);
        __threadfence();
        const unsigned prev = atomicAdd(&g_count, 1u);
        if (prev == (unsigned)(B_DIM - 1)) {
            const unsigned long long tot = atomicExch(&g_total, 0ull);
            out[0] = (float)((double)tot * (1.0 / 4294967296.0)
                             / (double)ROWS_TOTAL);
            atomicExch(&g_count, 0u);   // reset for next graph replay
        }
    }
}

extern "C" void kernel_launch(void* const* d_in, const int* in_sizes, int n_in,
                              void* d_out, int out_size)
{
    const float* y_pred = (const float*)d_in[0];
    const float* y_true = (const float*)d_in[1];
    const float* pO     = (const float*)d_in[2];
    const float* gumbel = (const float*)d_in[3];
    float* out = (float*)d_out;

    vlpl_kernel<<<B_DIM, S_DIM>>>(y_pred, y_true, pO, gumbel, out);
}

// round 16
// speedup vs baseline: 1.5632x; 1.5632x over previous
#include <cuda_runtime.h>

// VLPLLoss: sampled Plackett-Luce counterfactual expected reward.
//   d_in[0] y_pred : float32 [B, D, 1]   B=4096, D=120
//   d_in[1] y_true : float32 [B, D, 1]
//   d_in[2] pO_slot: float32 [K]         K=10
//   d_in[3] gumbel : float32 [S, B, D]   S=128
// out: scalar mean over (s,b) of sum_k pO[k] * y_true[b, topk_idx(s,b,k)]
//
// R16: warp-autonomous pipelines — NO block barrier in the main loop.
// Each warp owns 32 s-rows and a private double-buffered smem segment;
// LDG (reg staging) -> compute current chunk -> STS -> __syncwarp.
// Warps free-run and phase-shift, killing the barrier convoy that made the
// high-occupancy variants (R13/R15) slow. Sort math unchanged from the
// proven line: pruned Batcher top10of16 (60 CE) + half-cleaner + clean10v.
// Keys: bits(v) low 7 mantissa bits = (127 - doc), v = y_pred+gumbel+32 > 0
// -> uint order == float order, keys distinct, smaller doc wins ties (== top_k).

#define B_DIM 4096
#define D_DIM 120
#define S_DIM 128
#define K_SLOTS 10
#define ROWS_TOTAL (B_DIM * S_DIM)
#define BD_STRIDE (B_DIM * D_DIM)
#define STR 20   // smem row stride in floats (LDS.128 reads conflict-free)

__device__ unsigned long long g_total = 0ull;
__device__ unsigned int g_count = 0u;

// compare-exchange: ensure x >= y (IMNMX pair)
__device__ __forceinline__ void ce(unsigned& x, unsigned& y) {
    unsigned a = x, b = y;
    x = max(a, b);
    y = min(a, b);
}

// Batcher sort16 pruned to outputs 0..9 (sorted-desc top-10), 60 CE.
__device__ __forceinline__ void top10of16(unsigned* c) {
    ce(c[0],c[1]); ce(c[2],c[3]); ce(c[4],c[5]); ce(c[6],c[7]);
    ce(c[8],c[9]); ce(c[10],c[11]); ce(c[12],c[13]); ce(c[14],c[15]);
    ce(c[0],c[2]); ce(c[1],c[3]); ce(c[4],c[6]); ce(c[5],c[7]);
    ce(c[8],c[10]); ce(c[9],c[11]); ce(c[12],c[14]); ce(c[13],c[15]);
    ce(c[1],c[2]); ce(c[5],c[6]); ce(c[9],c[10]); ce(c[13],c[14]);
    ce(c[0],c[4]); ce(c[1],c[5]); ce(c[2],c[6]); ce(c[3],c[7]);
    ce(c[8],c[12]); ce(c[9],c[13]); ce(c[10],c[14]); ce(c[11],c[15]);
    ce(c[2],c[4]); ce(c[3],c[5]); ce(c[10],c[12]); ce(c[11],c[13]);
    ce(c[1],c[2]); ce(c[3],c[4]); ce(c[5],c[6]);
    ce(c[9],c[10]); ce(c[11],c[12]); ce(c[13],c[14]);
    ce(c[0],c[8]); ce(c[1],c[9]); ce(c[2],c[10]); ce(c[3],c[11]);
    ce(c[4],c[12]); ce(c[5],c[13]); ce(c[6],c[14]); ce(c[7],c[15]);
    ce(c[4],c[8]); ce(c[5],c[9]); ce(c[6],c[10]); ce(c[7],c[11]);
    ce(c[2],c[4]); ce(c[3],c[5]); ce(c[6],c[8]); ce(c[7],c[9]); ce(c[10],c[12]);
    ce(c[1],c[2]); ce(c[3],c[4]); ce(c[5],c[6]); ce(c[7],c[8]); ce(c[9],c[10]);
}

// Batcher sort8 descending (19 CE)
__device__ __forceinline__ void sort8(unsigned* c) {
    ce(c[0],c[1]); ce(c[2],c[3]); ce(c[4],c[5]); ce(c[6],c[7]);
    ce(c[0],c[2]); ce(c[1],c[3]); ce(c[4],c[6]); ce(c[5],c[7]);
    ce(c[1],c[2]); ce(c[5],c[6]);
    ce(c[0],c[4]); ce(c[1],c[5]); ce(c[2],c[6]); ce(c[3],c[7]);
    ce(c[2],c[4]); ce(c[3],c[5]);
    ce(c[1],c[2]); ce(c[3],c[4]); ce(c[5],c[6]);
}

// Bitonic cleanup for a length-10 valley (desc-then-asc) sequence (15 CE).
// Derivation: front-pad with +inf to 16 -> clean16's effective comparators.
__device__ __forceinline__ void clean10v(unsigned* m) {
    ce(m[0],m[8]); ce(m[1],m[9]);
    ce(m[0],m[1]);
    ce(m[2],m[6]); ce(m[3],m[7]); ce(m[4],m[8]); ce(m[5],m[9]);
    ce(m[2],m[4]); ce(m[3],m[5]); ce(m[6],m[8]); ce(m[7],m[9]);
    ce(m[2],m[3]); ce(m[4],m[5]); ce(m[6],m[7]); ce(m[8],m[9]);
}

__global__ __launch_bounds__(S_DIM, 8) void vlpl_kernel(
    const float* __restrict__ y_pred,
    const float* __restrict__ y_true,
    const float* __restrict__ pO,
    const float* __restrict__ gumbel,
    float* __restrict__ out)
{
    // per-warp private double-buffered staging: ws[warp][buf][32*STR]
    __shared__ __align__(16) float ws[4][2][32 * STR];
    __shared__ __align__(16) float yp_sh[D_DIM];
    __shared__ float yt_sh[S_DIM];      // reversed: yt_sh[127-d] = y_true[d]
    __shared__ float po_sh[K_SLOTS];
    __shared__ float wsum[4];

    const int b = blockIdx.x;
    const int t = threadIdx.x;
    const int w = t >> 5;          // warp id: owns s-rows [32w, 32w+32)
    const int lane = t & 31;

    if (t < D_DIM) {
        yp_sh[t] = y_pred[b * D_DIM + t] + 32.0f;
        yt_sh[127 - t] = y_true[b * D_DIM + t];
    }
    if (t < K_SLOTS) po_sh[t] = pO[t];
    __syncthreads();   // publish yp/yt/po once; no block barrier after this

    const size_t gb = (size_t)b * D_DIM;
    // 16-doc loader geometry (within warp): lane covers rows rl+8q, floats jl..jl+3
    const int jl = (lane & 3) * 4;
    const int rl = lane >> 2;          // 0..7
    // 8-doc remainder geometry: rows rl8+16q, floats 112+jl8..
    const int jl8 = (lane & 1) * 4;
    const int rl8 = lane >> 1;         // 0..15
    const float* __restrict__ gmain =
        gumbel + gb + (size_t)(w * 32 + rl) * BD_STRIDE + jl;
    const float* __restrict__ grem =
        gumbel + gb + (size_t)(w * 32 + rl8) * BD_STRIDE + 112 + jl8;

    float* const buf0 = ws[w][0];
    float* const buf1 = ws[w][1];

    // ---- prologue: chunk 0 -> buf0 ----
    {
        const float4 yp4 = *reinterpret_cast<const float4*>(&yp_sh[jl]);
#pragma unroll
        for (int q = 0; q < 4; ++q) {
            const float4 v = *reinterpret_cast<const float4*>(
                gmain + (size_t)q * 8 * BD_STRIDE);
            float4 x;
            x.x = yp4.x + v.x; x.y = yp4.y + v.y;
            x.z = yp4.z + v.z; x.w = yp4.w + v.w;
            *reinterpret_cast<float4*>(&buf0[(rl + 8 * q) * STR + jl]) = x;
        }
    }
    __syncwarp();

    unsigned L[10];
#pragma unroll
    for (int i = 0; i < 10; ++i) L[i] = 0u;

#pragma unroll 1
    for (int c = 0; c < 7; ++c) {
        // ---- (1) LDG next chunk into registers (consumed after compute) ----
        float4 pre0, pre1, pre2, pre3;
        if (c < 6) {
            const float* p = gmain + (c + 1) * 16;
            pre0 = *reinterpret_cast<const float4*>(p);
            pre1 = *reinterpret_cast<const float4*>(p + (size_t)8 * BD_STRIDE);
            pre2 = *reinterpret_cast<const float4*>(p + (size_t)16 * BD_STRIDE);
            pre3 = *reinterpret_cast<const float4*>(p + (size_t)24 * BD_STRIDE);
        } else {
            pre0 = *reinterpret_cast<const float4*>(grem);
            pre1 = *reinterpret_cast<const float4*>(grem + (size_t)16 * BD_STRIDE);
        }

        // ---- (2) compute chunk c from buf[c&1] (hides LDG latency) ----
        unsigned C[16];
        {
            const float* row = (c & 1) ? &buf1[lane * STR] : &buf0[lane * STR];
#pragma unroll
            for (int q = 0; q < 4; ++q) {
                const float4 v = *reinterpret_cast<const float4*>(row + 4 * q);
                const unsigned lb = (unsigned)(127 - c * 16 - 4 * q);
                C[4*q+0] = (__float_as_uint(v.x) & 0xFFFFFF80u) | lb;
                C[4*q+1] = (__float_as_uint(v.y) & 0xFFFFFF80u) | (lb - 1u);
                C[4*q+2] = (__float_as_uint(v.z) & 0xFFFFFF80u) | (lb - 2u);
                C[4*q+3] = (__float_as_uint(v.w) & 0xFFFFFF80u) | (lb - 3u);
            }
        }
        top10of16(C);
#pragma unroll
        for (int i = 0; i < 10; ++i) L[i] = max(L[i], C[9 - i]);
        clean10v(L);

        // ---- (3) fold y_pred, store prefetched chunk to the other buffer ----
        float* const dstbuf = ((c + 1) & 1) ? buf1 : buf0;
        if (c < 6) {
            const float4 yp4 =
                *reinterpret_cast<const float4*>(&yp_sh[(c + 1) * 16 + jl]);
            float4 x;
            x.x = yp4.x + pre0.x; x.y = yp4.y + pre0.y;
            x.z = yp4.z + pre0.z; x.w = yp4.w + pre0.w;
            *reinterpret_cast<float4*>(&dstbuf[rl * STR + jl]) = x;
            x.x = yp4.x + pre1.x; x.y = yp4.y + pre1.y;
            x.z = yp4.z + pre1.z; x.w = yp4.w + pre1.w;
            *reinterpret_cast<float4*>(&dstbuf[(rl + 8) * STR + jl]) = x;
            x.x = yp4.x + pre2.x; x.y = yp4.y + pre2.y;
            x.z = yp4.z + pre2.z; x.w = yp4.w + pre2.w;
            *reinterpret_cast<float4*>(&dstbuf[(rl + 16) * STR + jl]) = x;
            x.x = yp4.x + pre3.x; x.y = yp4.y + pre3.y;
            x.z = yp4.z + pre3.z; x.w = yp4.w + pre3.w;
            *reinterpret_cast<float4*>(&dstbuf[(rl + 24) * STR + jl]) = x;
        } else {
            const float4 yp4 =
                *reinterpret_cast<const float4*>(&yp_sh[112 + jl8]);
            float4 x;
            x.x = yp4.x + pre0.x; x.y = yp4.y + pre0.y;
            x.z = yp4.z + pre0.z; x.w = yp4.w + pre0.w;
            *reinterpret_cast<float4*>(&dstbuf[rl8 * STR + jl8]) = x;
            x.x = yp4.x + pre1.x; x.y = yp4.y + pre1.y;
            x.z = yp4.z + pre1.z; x.w = yp4.w + pre1.w;
            *reinterpret_cast<float4*>(&dstbuf[(rl8 + 16) * STR + jl8]) = x;
        }
        __syncwarp();   // warp-local publish; no block barrier
    }

    // ---- remainder compute: docs 112..119 from buf1 ----
    {
        unsigned C[8];
        const float* row = &buf1[lane * STR];
#pragma unroll
        for (int q = 0; q < 2; ++q) {
            const float4 v = *reinterpret_cast<const float4*>(row + 4 * q);
            const unsigned lb = (unsigned)(15 - 4 * q);
            C[4*q+0] = (__float_as_uint(v.x) & 0xFFFFFF80u) | lb;
            C[4*q+1] = (__float_as_uint(v.y) & 0xFFFFFF80u) | (lb - 1u);
            C[4*q+2] = (__float_as_uint(v.z) & 0xFFFFFF80u) | (lb - 2u);
            C[4*q+3] = (__float_as_uint(v.w) & 0xFFFFFF80u) | (lb - 3u);
        }
        sort8(C);
        // pad C[8]=C[9]=0 -> L[0],L[1] untouched by the half-cleaner stage
#pragma unroll
        for (int i = 2; i < 10; ++i) L[i] = max(L[i], C[9 - i]);
        clean10v(L);
    }

    // ---- decode top-10 (yt stored reversed -> direct index), weighted sum ----
    float reward = 0.0f;
#pragma unroll
    for (int k = 0; k < K_SLOTS; ++k)
        reward += po_sh[k] * yt_sh[(int)(L[k] & 127u)];

    // ---- reduction: warp shuffle -> per-warp partial -> one barrier ----
#pragma unroll
    for (int off = 16; off > 0; off >>= 1)
        reward += __shfl_down_sync(0xFFFFFFFFu, reward, off);
    if (lane == 0) wsum[w] = reward;
    __syncthreads();

    if (t == 0) {
        const float part = (wsum[0] + wsum[1]) + (wsum[2] + wsum[3]);
        // rewards nonnegative; block partial <= 1280 -> fits with 2^32 scale
        const unsigned long long fx =
            (unsigned long long)((double)part * 4294967296.0);
        atomicAdd(&g_total, fx);
        __threadfence();
        const unsigned prev = atomicAdd(&g_count, 1u);
        if (prev == (unsigned)(B_DIM - 1)) {
            const unsigned long long tot = atomicExch(&g_total, 0ull);
            out[0] = (float)((double)tot * (1.0 / 4294967296.0)
                             / (double)ROWS_TOTAL);
            atomicExch(&g_count, 0u);   // reset for next graph replay
        }
    }
}

extern "C" void kernel_launch(void* const* d_in, const int* in_sizes, int n_in,
                              void* d_out, int out_size)
{
    const float* y_pred = (const float*)d_in[0];
    const float* y_true = (const float*)d_in[1];
    const float* pO     = (const float*)d_in[2];
    const float* gumbel = (const float*)d_in[3];
    float* out = (float*)d_out;

    vlpl_kernel<<<B_DIM, S_DIM>>>(y_pred, y_true, pO, gumbel, out);
}